// round 9
// baseline (speedup 1.0000x reference)
#include <cuda_runtime.h>
#include <cstdint>
#include <cstddef>

#define HH 4
#define BB 32
#define NN 14
#define FF 1024

typedef unsigned long long ull;

__device__ __forceinline__ ull pk2(float a, float b) {
    ull r; asm("mov.b64 %0, {%1,%2};" : "=l"(r) : "f"(a), "f"(b)); return r;
}
__device__ __forceinline__ ull ffma2(ull a, ull b, ull c) {
    ull d; asm("fma.rn.f32x2 %0, %1, %2, %3;" : "=l"(d) : "l"(a), "l"(b), "l"(c)); return d;
}
__device__ __forceinline__ float2 upk2(ull a) {
    float2 f; asm("mov.b64 {%0,%1}, %2;" : "=f"(f.x), "=f"(f.y) : "l"(a)); return f;
}

// Scratch (allocation-free rules: __device__ globals)
__device__ float g_WhA[HH*BB*NN*FF];       // 7 MB (i half 0)
__device__ float g_WhB[HH*BB*NN*FF];       // 7 MB (i half 1)
__device__ float g_hp [HH*BB*NN*FF];       // 7 MB
__device__ float g_part[64*BB*FF];         // 8 MB split-K partials
__device__ float g_red [8*BB*FF];          // 1 MB k4 stage-A output

// ---------------------------------------------------------------------------
// K1: partial Wh over an i-half. 256 blocks = (h,b) x 2 halves.
// smem 56KB (x half staged as duplicated f32 pairs) -> 2 CTAs/SM, 16 warps/SM.
// W rows loaded directly as ulonglong2 (raw bytes == packed f32x2 operands).
// ---------------------------------------------------------------------------
__global__ void __launch_bounds__(256) k1(const float* __restrict__ x,
                                          const float* __restrict__ W) {
    extern __shared__ ull xs[];            // [512][14] duplicated pairs (56 KB)
    int bx   = blockIdx.x;
    int hb   = bx >> 1;
    int half = bx & 1;
    int b    = hb & 31;
    int i0   = half * 512;
    int tid  = threadIdx.x;

    const float* xb = x + (size_t)b * NN * FF + i0;
    for (int idx = tid; idx < NN*512/4; idx += 256) {
        int n  = idx >> 7;                 // 128 float4 groups per row
        int i4 = (idx & 127) * 4;
        float4 v = *(const float4*)(xb + n*FF + i4);
        xs[(i4+0)*NN + n] = pk2(v.x, v.x);
        xs[(i4+1)*NN + n] = pk2(v.y, v.y);
        xs[(i4+2)*NN + n] = pk2(v.z, v.z);
        xs[(i4+3)*NN + n] = pk2(v.w, v.w);
    }
    __syncthreads();

    const ulonglong2* Wt = (const ulonglong2*)(W + (size_t)hb * FF * FF) + (size_t)i0*256;
    ull acc[NN][2];
#pragma unroll
    for (int n = 0; n < NN; n++) { acc[n][0] = 0ull; acc[n][1] = 0ull; }

#pragma unroll 8
    for (int i = 0; i < 512; i++) {
        ulonglong2 w = Wt[i*256 + tid];
        const ulonglong2* xr = (const ulonglong2*)(xs + i*NN);
#pragma unroll
        for (int n2 = 0; n2 < 7; n2++) {
            ulonglong2 xx = xr[n2];        // broadcast LDS.128: rows 2*n2, 2*n2+1
            acc[2*n2  ][0] = ffma2(w.x, xx.x, acc[2*n2  ][0]);
            acc[2*n2  ][1] = ffma2(w.y, xx.x, acc[2*n2  ][1]);
            acc[2*n2+1][0] = ffma2(w.x, xx.y, acc[2*n2+1][0]);
            acc[2*n2+1][1] = ffma2(w.y, xx.y, acc[2*n2+1][1]);
        }
    }

    float* o = (half ? g_WhB : g_WhA) + (size_t)hb * NN * FF;
#pragma unroll
    for (int n = 0; n < NN; n++) {
        float2 p0 = upk2(acc[n][0]);
        float2 p1 = upk2(acc[n][1]);
        ((float4*)(o + n*FF))[tid] = make_float4(p0.x, p0.y, p1.x, p1.y);
    }
}

// ---------------------------------------------------------------------------
// K2: sum Wh halves into smem, attention scores + softmax(axis=n) +
// h_prime = att @ Wh. One block per (h,b), 448 threads = 14 warps.
// ---------------------------------------------------------------------------
__global__ void __launch_bounds__(448) k2(const float* __restrict__ adj,
                                          const float* __restrict__ a) {
    extern __shared__ float whs[];         // [14][1024] summed Wh (56 KB)
    __shared__ float s1[NN], s2[NN];
    __shared__ float att_s[NN][NN];
    int hb = blockIdx.x;
    int b  = hb & 31;
    int tid = threadIdx.x;
    int w = tid >> 5, lane = tid & 31;
    const float* h0 = g_WhA + (size_t)hb * NN * FF;
    const float* h1 = g_WhB + (size_t)hb * NN * FF;

    {   // warp w: sum halves for row w, store to smem, dot with a1/a2
        const float* a1 = a + (size_t)hb * 2 * FF;
        const float* a2 = a1 + FF;
        float p1 = 0.f, p2 = 0.f;
        for (int o = lane; o < FF; o += 32) {
            float wv = h0[w*FF + o] + h1[w*FF + o];
            whs[w*FF + o] = wv;
            p1 += wv * a1[o];
            p2 += wv * a2[o];
        }
#pragma unroll
        for (int d = 16; d; d >>= 1) {
            p1 += __shfl_down_sync(0xffffffffu, p1, d);
            p2 += __shfl_down_sync(0xffffffffu, p2, d);
        }
        if (lane == 0) { s1[w] = p1; s2[w] = p2; }
    }
    __syncthreads();

    // softmax over n (axis=2 of (H,B,N,N)) — thread m handles column m
    if (tid < NN) {
        int m = tid;
        float col[NN];
        float mx = -1e30f;
#pragma unroll
        for (int n = 0; n < NN; n++) {
            float e = s1[n] + s2[m];
            e = e > 0.f ? e : 0.2f * e;                       // leaky_relu
            e = (adj[b*NN*NN + n*NN + m] > 0.f) ? e : -9.0e15f;
            col[n] = e;
            mx = fmaxf(mx, e);
        }
        float sm = 0.f;
#pragma unroll
        for (int n = 0; n < NN; n++) { col[n] = expf(col[n] - mx); sm += col[n]; }
        float inv = 1.f / sm;
#pragma unroll
        for (int n = 0; n < NN; n++) att_s[n][m] = col[n] * inv;
    }
    __syncthreads();

    // h_prime[n,o] = sum_m att[n,m] * Wh[m,o]  (Wh from smem)
    float* hpB = g_hp + (size_t)hb * NN * FF;
    for (int o = tid; o < FF; o += 448) {
        float wv[NN];
#pragma unroll
        for (int m = 0; m < NN; m++) wv[m] = whs[m*FF + o];
#pragma unroll
        for (int n = 0; n < NN; n++) {
            float sacc = 0.f;
#pragma unroll
            for (int m = 0; m < NN; m++) sacc += att_s[n][m] * wv[m];
            hpB[n*FF + o] = sacc;
        }
    }
}

// ---------------------------------------------------------------------------
// K3: out_partial[p][b][o] = sum over k-range of hp[h,b,k] * fc_w[h,o,k]
// grid (4 o-tiles of 256, 4 h, 16 k-splits of 896). 256 THREADS (8 warps ->
// 2 warps/SMSP -> full FFMA2 issue rate). Thread tile 4b x 8o. fc_w tile
// transposed + XOR-swizzled; hp tile pre-duplicated u64 pairs.
// ---------------------------------------------------------------------------
__global__ void __launch_bounds__(256) k3(const float* __restrict__ fc_w) {
    __shared__ float w_s[32][256];
    __shared__ ull hp_s[32][34];           // [k][b] duplicated pairs
    int t  = threadIdx.x;
    int tx = t & 31, ty = t >> 5;          // ty in 0..7 -> 4 b rows each
    int tx2 = 2 * tx;
    int o0 = blockIdx.x * 256;
    int h  = blockIdx.y;
    int f0 = blockIdx.z * 896;
    const float* fw = fc_w + (size_t)h * FF * (NN*FF);
    const float* hp = g_hp + (size_t)h * BB * (NN*FF);

    ull acc[4][4];
#pragma unroll
    for (int i = 0; i < 4; i++)
#pragma unroll
        for (int j = 0; j < 4; j++) acc[i][j] = 0ull;

    int rr = t >> 3, kq = t & 7;           // rr in 0..31, kq in 0..7

    for (int ch = 0; ch < 28; ch++) {
        int kb = f0 + ch * 32;
        // stage fc_w tile (256 o x 32 k), transposed + XOR-swizzled
#pragma unroll
        for (int rep = 0; rep < 8; rep++) {
            int orow = rr + rep * 32;
            float4 v = *(const float4*)(fw + (size_t)(o0 + orow)*(NN*FF) + kb + kq*4);
            int k0 = kq * 4;
            w_s[k0+0][orow ^ ((k0+0) & 30)] = v.x;
            w_s[k0+1][orow ^ ((k0+1) & 30)] = v.y;
            w_s[k0+2][orow ^ ((k0+2) & 30)] = v.z;
            w_s[k0+3][orow ^ ((k0+3) & 30)] = v.w;
        }
        // stage hp tile (32 b x 32 k), transposed + duplicated pairs (1 rep)
        {
            int br = rr;
            float4 v = *(const float4*)(hp + (size_t)br*(NN*FF) + kb + kq*4);
            int k0 = kq * 4;
            hp_s[k0+0][br] = pk2(v.x, v.x);
            hp_s[k0+1][br] = pk2(v.y, v.y);
            hp_s[k0+2][br] = pk2(v.z, v.z);
            hp_s[k0+3][br] = pk2(v.w, v.w);
        }
        __syncthreads();

#pragma unroll 8
        for (int k = 0; k < 32; k++) {
            int s  = k & 30;
            int pc = tx2 ^ s;
            ull w0 = *(const ull*)&w_s[k][pc];
            ull w1 = *(const ull*)&w_s[k][64  + pc];
            ull w2 = *(const ull*)&w_s[k][128 + pc];
            ull w3 = *(const ull*)&w_s[k][192 + pc];
            const ulonglong2* hr = (const ulonglong2*)&hp_s[k][ty*4];
            ulonglong2 x01 = hr[0], x23 = hr[1];
            ull xb[4] = {x01.x, x01.y, x23.x, x23.y};
#pragma unroll
            for (int bi = 0; bi < 4; bi++) {
                acc[bi][0] = ffma2(w0, xb[bi], acc[bi][0]);
                acc[bi][1] = ffma2(w1, xb[bi], acc[bi][1]);
                acc[bi][2] = ffma2(w2, xb[bi], acc[bi][2]);
                acc[bi][3] = ffma2(w3, xb[bi], acc[bi][3]);
            }
        }
        __syncthreads();
    }

    float* pt = g_part + ((size_t)(h*16 + blockIdx.z)) * BB * FF;
#pragma unroll
    for (int bi = 0; bi < 4; bi++) {
        int b = ty * 4 + bi;
#pragma unroll
        for (int p = 0; p < 4; p++) {
            float2 v = upk2(acc[bi][p]);
            int oc = o0 + p*64 + tx2;
            pt[b*FF + oc]     = v.x;
            pt[b*FF + oc + 1] = v.y;
        }
    }
}

// ---------------------------------------------------------------------------
// K4a: stage-A reduction. grid (8 partial-groups, 32 b), 256 threads.
// Each thread sums 8 partials for one float4 column group -> g_red.
// ---------------------------------------------------------------------------
__global__ void __launch_bounds__(256) k4a() {
    int p8 = blockIdx.x, b = blockIdx.y, t = threadIdx.x;
    const float4* gp = (const float4*)g_part;
    float4 s = make_float4(0.f, 0.f, 0.f, 0.f);
#pragma unroll
    for (int j = 0; j < 8; j++) {
        float4 v = gp[(size_t)((p8*8 + j)*BB + b) * (FF/4) + t];
        s.x += v.x; s.y += v.y; s.z += v.z; s.w += v.w;
    }
    ((float4*)g_red)[(size_t)(p8*BB + b) * (FF/4) + t] = s;
}

// ---------------------------------------------------------------------------
// K4b: out[b,o] = log_softmax_o( sum_p8 red[p8][b][o] + sum_h fc_b[h][o] )
// ---------------------------------------------------------------------------
__global__ void __launch_bounds__(256) k4b(const float* __restrict__ fc_b,
                                           float* __restrict__ out) {
    int b = blockIdx.x, t = threadIdx.x;
    int lane = t & 31, wrp = t >> 5;
    __shared__ float red[8];

    float4 s = make_float4(0.f, 0.f, 0.f, 0.f);
    const float4* gr = (const float4*)g_red;
#pragma unroll
    for (int p8 = 0; p8 < 8; p8++) {
        float4 v = gr[(size_t)(p8*BB + b) * (FF/4) + t];
        s.x += v.x; s.y += v.y; s.z += v.z; s.w += v.w;
    }
    const float4* fb = (const float4*)fc_b;
#pragma unroll
    for (int h = 0; h < HH; h++) {
        float4 v = fb[h*(FF/4) + t];
        s.x += v.x; s.y += v.y; s.z += v.z; s.w += v.w;
    }

    // block max
    float m = fmaxf(fmaxf(s.x, s.y), fmaxf(s.z, s.w));
#pragma unroll
    for (int d = 16; d; d >>= 1) m = fmaxf(m, __shfl_xor_sync(0xffffffffu, m, d));
    if (lane == 0) red[wrp] = m;
    __syncthreads();
    float mx = fmaxf(fmaxf(fmaxf(red[0], red[1]), fmaxf(red[2], red[3])),
                     fmaxf(fmaxf(red[4], red[5]), fmaxf(red[6], red[7])));
    __syncthreads();

    // block sum of exp
    float es = expf(s.x - mx) + expf(s.y - mx) + expf(s.z - mx) + expf(s.w - mx);
#pragma unroll
    for (int d = 16; d; d >>= 1) es += __shfl_xor_sync(0xffffffffu, es, d);
    if (lane == 0) red[wrp] = es;
    __syncthreads();
    float tot = red[0] + red[1] + red[2] + red[3] + red[4] + red[5] + red[6] + red[7];
    float lse = logf(tot) + mx;

    ((float4*)out)[b*(FF/4) + t] =
        make_float4(s.x - lse, s.y - lse, s.z - lse, s.w - lse);
}

// ---------------------------------------------------------------------------
extern "C" void kernel_launch(void* const* d_in, const int* in_sizes, int n_in,
                              void* d_out, int out_size) {
    const float *x = nullptr, *adj = nullptr, *W = nullptr, *a = nullptr;
    const float *fcw = nullptr, *fcb = nullptr;
    for (int i = 0; i < n_in; i++) {
        switch (in_sizes[i]) {
            case 458752:    x   = (const float*)d_in[i]; break;  // x (32,14,1024)
            case 6272:      adj = (const float*)d_in[i]; break;  // adj (32,14,14)
            case 134217728: W   = (const float*)d_in[i]; break;  // W (4,32,1024,1024)
            case 262144:    a   = (const float*)d_in[i]; break;  // a (4,32,2048,1)
            case 58720256:  fcw = (const float*)d_in[i]; break;  // fc_w (4,1024,14336)
            case 4096:      fcb = (const float*)d_in[i]; break;  // fc_b (4,1024)
        }
    }
    cudaFuncSetAttribute(k1, cudaFuncAttributeMaxDynamicSharedMemorySize, 512*NN*8);
    cudaFuncSetAttribute(k2, cudaFuncAttributeMaxDynamicSharedMemorySize, NN*FF*4);
    k1<<<HH*BB*2, 256, 512*NN*8>>>(x, W);
    k2<<<HH*BB, 448, NN*FF*4>>>(adj, a);
    k3<<<dim3(4, 4, 16), 256>>>(fcw);
    k4a<<<dim3(8, BB), 256>>>();
    k4b<<<BB, 256>>>(fcb, (float*)d_out);
}

// round 14
// speedup vs baseline: 1.7068x; 1.7068x over previous
#include <cuda_runtime.h>
#include <cstdint>
#include <cstddef>

#define HH 4
#define BB 32
#define NN 14
#define FF 1024
#define NF (NN*FF)   // 14336

typedef unsigned long long ull;

__device__ __forceinline__ ull pk2(float a, float b) {
    ull r; asm("mov.b64 %0, {%1,%2};" : "=l"(r) : "f"(a), "f"(b)); return r;
}
__device__ __forceinline__ ull ffma2(ull a, ull b, ull c) {
    ull d; asm("fma.rn.f32x2 %0, %1, %2, %3;" : "=l"(d) : "l"(a), "l"(b), "l"(c)); return d;
}
__device__ __forceinline__ float2 upk2(ull a) {
    float2 f; asm("mov.b64 {%0,%1}, %2;" : "=f"(f.x), "=f"(f.y) : "l"(a)); return f;
}

// Scratch (allocation-free rules: __device__ globals)
__device__ float g_WhA[HH*BB*NN*FF];        // 7 MB (i half 0)
__device__ float g_WhB[HH*BB*NN*FF];        // 7 MB (i half 1)
__device__ float g_hp [HH*BB*NN*FF];        // 7 MB
__device__ float g_part[128*BB*FF];         // 16 MB split-K partials
__device__ float g_red [16*BB*FF];          // 2 MB k4 stage-A output

// dummy: shifts the ncu-captured launch slot (idx 3) onto k1
__global__ void kdummy() {}

// ---------------------------------------------------------------------------
// K1: partial Wh over an i-half. 256 blocks = (h,b) x 2 halves.
// Software-pipelined: rolling 4-deep register prefetch of W rows (LDG.128),
// LDS kept adjacent to use, accumulators in f32x2 pairs. Bounded at 2 CTA/SM.
// ---------------------------------------------------------------------------
__global__ void __launch_bounds__(256, 2) k1(const float* __restrict__ x,
                                             const float* __restrict__ W) {
    extern __shared__ ull xs[];             // [512][14] duplicated pairs (56 KB)
    int bx   = blockIdx.x;
    int hb   = bx >> 1;
    int half = bx & 1;
    int b    = hb & 31;
    int i0   = half * 512;
    int tid  = threadIdx.x;

    const float* xb = x + (size_t)b * NN * FF + i0;
    for (int idx = tid; idx < NN*512/4; idx += 256) {
        int n  = idx >> 7;
        int i4 = (idx & 127) * 4;
        float4 v = *(const float4*)(xb + n*FF + i4);
        xs[(i4+0)*NN + n] = pk2(v.x, v.x);
        xs[(i4+1)*NN + n] = pk2(v.y, v.y);
        xs[(i4+2)*NN + n] = pk2(v.z, v.z);
        xs[(i4+3)*NN + n] = pk2(v.w, v.w);
    }
    __syncthreads();

    const ulonglong2* Wp =
        (const ulonglong2*)(W + (size_t)hb * FF * FF) + (size_t)i0 * 256 + tid;

    ulonglong2 wbuf[4];
#pragma unroll
    for (int p = 0; p < 4; p++) wbuf[p] = Wp[(size_t)p * 256];

    ull acc[NN][2];
#pragma unroll
    for (int n = 0; n < NN; n++) { acc[n][0] = 0ull; acc[n][1] = 0ull; }

#pragma unroll 4
    for (int i = 0; i < 512; i++) {
        ulonglong2 w = wbuf[i & 3];
        int ipf = (i + 4 < 512) ? (i + 4) : 511;   // tail: redundant reload, harmless
        wbuf[i & 3] = Wp[(size_t)ipf * 256];
        const ulonglong2* xr = (const ulonglong2*)(xs + i*NN);
#pragma unroll
        for (int n2 = 0; n2 < 7; n2++) {
            ulonglong2 xx = xr[n2];         // broadcast LDS.128
            acc[2*n2  ][0] = ffma2(w.x, xx.x, acc[2*n2  ][0]);
            acc[2*n2  ][1] = ffma2(w.y, xx.x, acc[2*n2  ][1]);
            acc[2*n2+1][0] = ffma2(w.x, xx.y, acc[2*n2+1][0]);
            acc[2*n2+1][1] = ffma2(w.y, xx.y, acc[2*n2+1][1]);
        }
    }

    float* o = (half ? g_WhB : g_WhA) + (size_t)hb * NN * FF;
#pragma unroll
    for (int n = 0; n < NN; n++) {
        float2 p0 = upk2(acc[n][0]);
        float2 p1 = upk2(acc[n][1]);
        ((float4*)(o + n*FF))[tid] = make_float4(p0.x, p0.y, p1.x, p1.y);
    }
}

// ---------------------------------------------------------------------------
// K2: sum Wh halves into smem, attention scores + softmax(axis=n) +
// h_prime = att @ Wh. One block per (h,b), 448 threads = 14 warps.
// ---------------------------------------------------------------------------
__global__ void __launch_bounds__(448) k2(const float* __restrict__ adj,
                                          const float* __restrict__ a) {
    extern __shared__ float whs[];          // [14][1024] summed Wh (56 KB)
    __shared__ float s1[NN], s2[NN];
    __shared__ float att_s[NN][NN];
    int hb = blockIdx.x;
    int b  = hb & 31;
    int tid = threadIdx.x;
    int w = tid >> 5, lane = tid & 31;
    const float* h0 = g_WhA + (size_t)hb * NN * FF;
    const float* h1 = g_WhB + (size_t)hb * NN * FF;

    {
        const float* a1 = a + (size_t)hb * 2 * FF;
        const float* a2 = a1 + FF;
        float p1 = 0.f, p2 = 0.f;
        for (int o = lane; o < FF; o += 32) {
            float wv = h0[w*FF + o] + h1[w*FF + o];
            whs[w*FF + o] = wv;
            p1 += wv * a1[o];
            p2 += wv * a2[o];
        }
#pragma unroll
        for (int d = 16; d; d >>= 1) {
            p1 += __shfl_down_sync(0xffffffffu, p1, d);
            p2 += __shfl_down_sync(0xffffffffu, p2, d);
        }
        if (lane == 0) { s1[w] = p1; s2[w] = p2; }
    }
    __syncthreads();

    if (tid < NN) {
        int m = tid;
        float col[NN];
        float mx = -1e30f;
#pragma unroll
        for (int n = 0; n < NN; n++) {
            float e = s1[n] + s2[m];
            e = e > 0.f ? e : 0.2f * e;                       // leaky_relu
            e = (adj[b*NN*NN + n*NN + m] > 0.f) ? e : -9.0e15f;
            col[n] = e;
            mx = fmaxf(mx, e);
        }
        float sm = 0.f;
#pragma unroll
        for (int n = 0; n < NN; n++) { col[n] = expf(col[n] - mx); sm += col[n]; }
        float inv = 1.f / sm;
#pragma unroll
        for (int n = 0; n < NN; n++) att_s[n][m] = col[n] * inv;
    }
    __syncthreads();

    float* hpB = g_hp + (size_t)hb * NN * FF;
    for (int o = tid; o < FF; o += 448) {
        float wv[NN];
#pragma unroll
        for (int m = 0; m < NN; m++) wv[m] = whs[m*FF + o];
#pragma unroll
        for (int n = 0; n < NN; n++) {
            float sacc = 0.f;
#pragma unroll
            for (int m = 0; m < NN; m++) sacc += att_s[n][m] * wv[m];
            hpB[n*FF + o] = sacc;
        }
    }
}

// ---------------------------------------------------------------------------
// K3: out_partial[p][b][o] = sum over k-range of hp[h,b,k] * fc_w[h,o,k]
// grid (4 o-tiles of 256, 4 h, 32 k-splits of 448). 256 threads.
// Register prefetch of next chunk's tiles issued right after the barrier so
// staging DRAM latency overlaps the compute phase.
// ---------------------------------------------------------------------------
__global__ void __launch_bounds__(256, 2) k3(const float* __restrict__ fc_w) {
    __shared__ float w_s[32][256];
    __shared__ ull hp_s[32][34];            // [k][b] duplicated pairs
    int t  = threadIdx.x;
    int tx = t & 31, ty = t >> 5;           // ty 0..7 -> 4 b rows each
    int tx2 = 2 * tx;
    int o0 = blockIdx.x * 256;
    int h  = blockIdx.y;
    int f0 = blockIdx.z * 448;
    const float* fw = fc_w + (size_t)h * FF * NF;
    const float* hp = g_hp + (size_t)h * BB * NF;

    int rr = t >> 3, kq = t & 7;            // rr 0..31, kq 0..7
    const float* fwb = fw + (size_t)(o0 + rr) * NF + kq*4;
    const float* hpb = hp + (size_t)rr * NF + kq*4;

    float4 pw[8]; float4 ph;
    {
        int kb = f0;
#pragma unroll
        for (int rep = 0; rep < 8; rep++)
            pw[rep] = *(const float4*)(fwb + (size_t)rep*32*NF + kb);
        ph = *(const float4*)(hpb + kb);
    }

    ull acc[4][4];
#pragma unroll
    for (int i = 0; i < 4; i++)
#pragma unroll
        for (int j = 0; j < 4; j++) acc[i][j] = 0ull;

    int k0 = kq * 4;
    int s0 = k0, s2 = k0 + 2;               // (k0+j)&30 for j=0,1 and 2,3

    for (int ch = 0; ch < 14; ch++) {
        // STS phase: dump prefetched regs into smem
#pragma unroll
        for (int rep = 0; rep < 8; rep++) {
            int orow = rr + rep * 32;
            w_s[k0+0][orow ^ s0] = pw[rep].x;
            w_s[k0+1][orow ^ s0] = pw[rep].y;
            w_s[k0+2][orow ^ s2] = pw[rep].z;
            w_s[k0+3][orow ^ s2] = pw[rep].w;
        }
        hp_s[k0+0][rr] = pk2(ph.x, ph.x);
        hp_s[k0+1][rr] = pk2(ph.y, ph.y);
        hp_s[k0+2][rr] = pk2(ph.z, ph.z);
        hp_s[k0+3][rr] = pk2(ph.w, ph.w);
        __syncthreads();

        // prefetch next chunk (overlaps with compute below)
        if (ch < 13) {
            int kb = f0 + (ch + 1) * 32;
#pragma unroll
            for (int rep = 0; rep < 8; rep++)
                pw[rep] = *(const float4*)(fwb + (size_t)rep*32*NF + kb);
            ph = *(const float4*)(hpb + kb);
        }

#pragma unroll 4
        for (int k = 0; k < 32; k++) {
            int s  = k & 30;
            int pc = tx2 ^ s;
            ull w0 = *(const ull*)&w_s[k][pc];
            ull w1 = *(const ull*)&w_s[k][64  + pc];
            ull w2 = *(const ull*)&w_s[k][128 + pc];
            ull w3 = *(const ull*)&w_s[k][192 + pc];
            const ulonglong2* hr = (const ulonglong2*)&hp_s[k][ty*4];
            ulonglong2 x01 = hr[0], x23 = hr[1];
            ull xb[4] = {x01.x, x01.y, x23.x, x23.y};
#pragma unroll
            for (int bi = 0; bi < 4; bi++) {
                acc[bi][0] = ffma2(w0, xb[bi], acc[bi][0]);
                acc[bi][1] = ffma2(w1, xb[bi], acc[bi][1]);
                acc[bi][2] = ffma2(w2, xb[bi], acc[bi][2]);
                acc[bi][3] = ffma2(w3, xb[bi], acc[bi][3]);
            }
        }
        __syncthreads();
    }

    float* pt = g_part + ((size_t)(h*32 + blockIdx.z)) * BB * FF;
#pragma unroll
    for (int bi = 0; bi < 4; bi++) {
        int b = ty * 4 + bi;
#pragma unroll
        for (int p = 0; p < 4; p++) {
            float2 v = upk2(acc[bi][p]);
            int oc = o0 + p*64 + tx2;
            pt[b*FF + oc]     = v.x;
            pt[b*FF + oc + 1] = v.y;
        }
    }
}

// ---------------------------------------------------------------------------
// K4a: stage-A reduction. grid (16 partial-groups, 32 b), 256 threads.
// Each thread sums 8 slices for one float4 column group -> g_red.
// ---------------------------------------------------------------------------
__global__ void __launch_bounds__(256) k4a() {
    int pg = blockIdx.x, b = blockIdx.y, t = threadIdx.x;
    const float4* gp = (const float4*)g_part;
    float4 s = make_float4(0.f, 0.f, 0.f, 0.f);
#pragma unroll
    for (int j = 0; j < 8; j++) {
        float4 v = gp[(size_t)((pg*8 + j)*BB + b) * (FF/4) + t];
        s.x += v.x; s.y += v.y; s.z += v.z; s.w += v.w;
    }
    ((float4*)g_red)[(size_t)(pg*BB + b) * (FF/4) + t] = s;
}

// ---------------------------------------------------------------------------
// K4b: out[b,o] = log_softmax_o( sum_pg red[pg][b][o] + sum_h fc_b[h][o] )
// ---------------------------------------------------------------------------
__global__ void __launch_bounds__(256) k4b(const float* __restrict__ fc_b,
                                           float* __restrict__ out) {
    int b = blockIdx.x, t = threadIdx.x;
    int lane = t & 31, wrp = t >> 5;
    __shared__ float red[8];

    float4 s = make_float4(0.f, 0.f, 0.f, 0.f);
    const float4* gr = (const float4*)g_red;
#pragma unroll
    for (int pg = 0; pg < 16; pg++) {
        float4 v = gr[(size_t)(pg*BB + b) * (FF/4) + t];
        s.x += v.x; s.y += v.y; s.z += v.z; s.w += v.w;
    }
    const float4* fb = (const float4*)fc_b;
#pragma unroll
    for (int h = 0; h < HH; h++) {
        float4 v = fb[h*(FF/4) + t];
        s.x += v.x; s.y += v.y; s.z += v.z; s.w += v.w;
    }

    float m = fmaxf(fmaxf(s.x, s.y), fmaxf(s.z, s.w));
#pragma unroll
    for (int d = 16; d; d >>= 1) m = fmaxf(m, __shfl_xor_sync(0xffffffffu, m, d));
    if (lane == 0) red[wrp] = m;
    __syncthreads();
    float mx = fmaxf(fmaxf(fmaxf(red[0], red[1]), fmaxf(red[2], red[3])),
                     fmaxf(fmaxf(red[4], red[5]), fmaxf(red[6], red[7])));
    __syncthreads();

    float es = expf(s.x - mx) + expf(s.y - mx) + expf(s.z - mx) + expf(s.w - mx);
#pragma unroll
    for (int d = 16; d; d >>= 1) es += __shfl_xor_sync(0xffffffffu, es, d);
    if (lane == 0) red[wrp] = es;
    __syncthreads();
    float tot = red[0] + red[1] + red[2] + red[3] + red[4] + red[5] + red[6] + red[7];
    float lse = logf(tot) + mx;

    ((float4*)out)[b*(FF/4) + t] =
        make_float4(s.x - lse, s.y - lse, s.z - lse, s.w - lse);
}

// ---------------------------------------------------------------------------
extern "C" void kernel_launch(void* const* d_in, const int* in_sizes, int n_in,
                              void* d_out, int out_size) {
    const float *x = nullptr, *adj = nullptr, *W = nullptr, *a = nullptr;
    const float *fcw = nullptr, *fcb = nullptr;
    for (int i = 0; i < n_in; i++) {
        switch (in_sizes[i]) {
            case 458752:    x   = (const float*)d_in[i]; break;  // x (32,14,1024)
            case 6272:      adj = (const float*)d_in[i]; break;  // adj (32,14,14)
            case 134217728: W   = (const float*)d_in[i]; break;  // W (4,32,1024,1024)
            case 262144:    a   = (const float*)d_in[i]; break;  // a (4,32,2048,1)
            case 58720256:  fcw = (const float*)d_in[i]; break;  // fc_w (4,1024,14336)
            case 4096:      fcb = (const float*)d_in[i]; break;  // fc_b (4,1024)
        }
    }
    cudaFuncSetAttribute(k1, cudaFuncAttributeMaxDynamicSharedMemorySize, 512*NN*8);
    cudaFuncSetAttribute(k2, cudaFuncAttributeMaxDynamicSharedMemorySize, NN*FF*4);
    // 3 dummies shift the ncu capture slot (launch idx 3) onto k1
    kdummy<<<1, 1>>>();
    kdummy<<<1, 1>>>();
    kdummy<<<1, 1>>>();
    k1<<<HH*BB*2, 256, 512*NN*8>>>(x, W);
    k2<<<HH*BB, 448, NN*FF*4>>>(adj, a);
    k3<<<dim3(4, 4, 32), 256>>>(fcw);
    k4a<<<dim3(16, BB), 256>>>();
    k4b<<<BB, 256>>>(fcb, (float*)d_out);
}

// round 15
// speedup vs baseline: 1.7820x; 1.0441x over previous
#include <cuda_runtime.h>
#include <cstdint>
#include <cstddef>

#define HH 4
#define BB 32
#define NN 14
#define FF 1024
#define NF (NN*FF)   // 14336

typedef unsigned long long ull;

__device__ __forceinline__ ull pk2(float a, float b) {
    ull r; asm("mov.b64 %0, {%1,%2};" : "=l"(r) : "f"(a), "f"(b)); return r;
}
__device__ __forceinline__ ull ffma2(ull a, ull b, ull c) {
    ull d; asm("fma.rn.f32x2 %0, %1, %2, %3;" : "=l"(d) : "l"(a), "l"(b), "l"(c)); return d;
}
__device__ __forceinline__ float2 upk2(ull a) {
    float2 f; asm("mov.b64 {%0,%1}, %2;" : "=f"(f.x), "=f"(f.y) : "l"(a)); return f;
}

// Scratch (allocation-free rules: __device__ globals)
__device__ float g_WhA[HH*BB*NN*FF];        // 7 MB (i half 0)
__device__ float g_WhB[HH*BB*NN*FF];        // 7 MB (i half 1)
__device__ float g_hp [HH*BB*NN*FF];        // 7 MB
__device__ float g_part[128*BB*FF];         // 16 MB split-K partials
__device__ float g_red [16*BB*FF];          // 2 MB k4 stage-A output

// dummy: aligns the ncu capture slot (launch idx 3) onto k3 this round
__global__ void kdummy() {}

// ---------------------------------------------------------------------------
// K1: partial Wh over an i-half. 256 blocks = (h,b) x 2 halves, 512 threads.
// n-rows split into 2 groups of 7: thread (g, c) owns rows 7g..7g+6, cols
// 4c..4c+3. acc = 28 regs (half of before) -> 2 CTA/SM at 512 thr = 32
// warps/SM. Per i: 1 LDG.128 (group 1 dups group 0 -> L1 hit), 4 LDS.128
// from the group's padded 8-slot duplicated-pair array, 14 FFMA2.
// ---------------------------------------------------------------------------
__global__ void __launch_bounds__(512, 2) k1(const float* __restrict__ x,
                                             const float* __restrict__ W) {
    extern __shared__ ull xs[];             // 2 groups x [512][8] pairs (64 KB)
    int bx   = blockIdx.x;
    int hb   = bx >> 1;
    int half = bx & 1;
    int b    = hb & 31;
    int i0   = half * 512;
    int tid  = threadIdx.x;
    int g    = tid >> 8;                    // group 0/1
    int c    = tid & 255;                   // col group (4 cols)

    // stage x half as duplicated pairs into per-group padded arrays
    const float* xb = x + (size_t)b * NN * FF + i0;
    for (int idx = tid; idx < NN*512/4; idx += 512) {
        int n  = idx >> 7;                  // 0..13
        int i4 = (idx & 127) * 4;
        int gg = (n >= 7) ? 1 : 0;
        int sl = n - 7*gg;
        ull* dst = xs + gg*4096 + sl;
        float4 v = *(const float4*)(xb + n*FF + i4);
        dst[(i4+0)*8] = pk2(v.x, v.x);
        dst[(i4+1)*8] = pk2(v.y, v.y);
        dst[(i4+2)*8] = pk2(v.z, v.z);
        dst[(i4+3)*8] = pk2(v.w, v.w);
    }
    __syncthreads();

    const ulonglong2* Wp =
        (const ulonglong2*)(W + (size_t)hb * FF * FF) + (size_t)i0 * 256 + c;
    const ull* xg = xs + g * 4096;

    ulonglong2 wbuf[2];
    wbuf[0] = Wp[0];
    wbuf[1] = Wp[256];

    ull acc[7][2];
#pragma unroll
    for (int r = 0; r < 7; r++) { acc[r][0] = 0ull; acc[r][1] = 0ull; }

#pragma unroll 4
    for (int i = 0; i < 512; i++) {
        ulonglong2 w = wbuf[i & 1];
        int ipf = (i + 2 < 512) ? (i + 2) : 511;   // tail: redundant reload
        wbuf[i & 1] = Wp[(size_t)ipf * 256];
        const ulonglong2* xr = (const ulonglong2*)(xg + i*8);
        ulonglong2 x01 = xr[0];
        ulonglong2 x23 = xr[1];
        ulonglong2 x45 = xr[2];
        ulonglong2 x6p = xr[3];             // .y = padding, never used
        acc[0][0] = ffma2(w.x, x01.x, acc[0][0]);
        acc[0][1] = ffma2(w.y, x01.x, acc[0][1]);
        acc[1][0] = ffma2(w.x, x01.y, acc[1][0]);
        acc[1][1] = ffma2(w.y, x01.y, acc[1][1]);
        acc[2][0] = ffma2(w.x, x23.x, acc[2][0]);
        acc[2][1] = ffma2(w.y, x23.x, acc[2][1]);
        acc[3][0] = ffma2(w.x, x23.y, acc[3][0]);
        acc[3][1] = ffma2(w.y, x23.y, acc[3][1]);
        acc[4][0] = ffma2(w.x, x45.x, acc[4][0]);
        acc[4][1] = ffma2(w.y, x45.x, acc[4][1]);
        acc[5][0] = ffma2(w.x, x45.y, acc[5][0]);
        acc[5][1] = ffma2(w.y, x45.y, acc[5][1]);
        acc[6][0] = ffma2(w.x, x6p.x, acc[6][0]);
        acc[6][1] = ffma2(w.y, x6p.x, acc[6][1]);
    }

    float* o = (half ? g_WhB : g_WhA) + (size_t)hb * NN * FF + (size_t)g*7*FF;
#pragma unroll
    for (int r = 0; r < 7; r++) {
        float2 p0 = upk2(acc[r][0]);
        float2 p1 = upk2(acc[r][1]);
        ((float4*)(o + r*FF))[c] = make_float4(p0.x, p0.y, p1.x, p1.y);
    }
}

// ---------------------------------------------------------------------------
// K2: sum Wh halves into smem, attention scores + softmax(axis=n) +
// h_prime = att @ Wh. One block per (h,b), 448 threads = 14 warps.
// ---------------------------------------------------------------------------
__global__ void __launch_bounds__(448) k2(const float* __restrict__ adj,
                                          const float* __restrict__ a) {
    extern __shared__ float whs[];          // [14][1024] summed Wh (56 KB)
    __shared__ float s1[NN], s2[NN];
    __shared__ float att_s[NN][NN];
    int hb = blockIdx.x;
    int b  = hb & 31;
    int tid = threadIdx.x;
    int w = tid >> 5, lane = tid & 31;
    const float* h0 = g_WhA + (size_t)hb * NN * FF;
    const float* h1 = g_WhB + (size_t)hb * NN * FF;

    {
        const float* a1 = a + (size_t)hb * 2 * FF;
        const float* a2 = a1 + FF;
        float p1 = 0.f, p2 = 0.f;
        for (int o = lane; o < FF; o += 32) {
            float wv = h0[w*FF + o] + h1[w*FF + o];
            whs[w*FF + o] = wv;
            p1 += wv * a1[o];
            p2 += wv * a2[o];
        }
#pragma unroll
        for (int d = 16; d; d >>= 1) {
            p1 += __shfl_down_sync(0xffffffffu, p1, d);
            p2 += __shfl_down_sync(0xffffffffu, p2, d);
        }
        if (lane == 0) { s1[w] = p1; s2[w] = p2; }
    }
    __syncthreads();

    if (tid < NN) {
        int m = tid;
        float col[NN];
        float mx = -1e30f;
#pragma unroll
        for (int n = 0; n < NN; n++) {
            float e = s1[n] + s2[m];
            e = e > 0.f ? e : 0.2f * e;                       // leaky_relu
            e = (adj[b*NN*NN + n*NN + m] > 0.f) ? e : -9.0e15f;
            col[n] = e;
            mx = fmaxf(mx, e);
        }
        float sm = 0.f;
#pragma unroll
        for (int n = 0; n < NN; n++) { col[n] = expf(col[n] - mx); sm += col[n]; }
        float inv = 1.f / sm;
#pragma unroll
        for (int n = 0; n < NN; n++) att_s[n][m] = col[n] * inv;
    }
    __syncthreads();

    float* hpB = g_hp + (size_t)hb * NN * FF;
    for (int o = tid; o < FF; o += 448) {
        float wv[NN];
#pragma unroll
        for (int m = 0; m < NN; m++) wv[m] = whs[m*FF + o];
#pragma unroll
        for (int n = 0; n < NN; n++) {
            float sacc = 0.f;
#pragma unroll
            for (int m = 0; m < NN; m++) sacc += att_s[n][m] * wv[m];
            hpB[n*FF + o] = sacc;
        }
    }
}

// ---------------------------------------------------------------------------
// K3: out_partial[p][b][o] = sum over k-range of hp[h,b,k] * fc_w[h,o,k]
// grid (4 o-tiles of 256, 4 h, 32 k-splits of 448). 256 threads.
// Register prefetch of next chunk's tiles overlaps staging latency.
// ---------------------------------------------------------------------------
__global__ void __launch_bounds__(256, 2) k3(const float* __restrict__ fc_w) {
    __shared__ float w_s[32][256];
    __shared__ ull hp_s[32][34];            // [k][b] duplicated pairs
    int t  = threadIdx.x;
    int tx = t & 31, ty = t >> 5;           // ty 0..7 -> 4 b rows each
    int tx2 = 2 * tx;
    int o0 = blockIdx.x * 256;
    int h  = blockIdx.y;
    int f0 = blockIdx.z * 448;
    const float* fw = fc_w + (size_t)h * FF * NF;
    const float* hp = g_hp + (size_t)h * BB * NF;

    int rr = t >> 3, kq = t & 7;            // rr 0..31, kq 0..7
    const float* fwb = fw + (size_t)(o0 + rr) * NF + kq*4;
    const float* hpb = hp + (size_t)rr * NF + kq*4;

    float4 pw[8]; float4 ph;
    {
        int kb = f0;
#pragma unroll
        for (int rep = 0; rep < 8; rep++)
            pw[rep] = *(const float4*)(fwb + (size_t)rep*32*NF + kb);
        ph = *(const float4*)(hpb + kb);
    }

    ull acc[4][4];
#pragma unroll
    for (int i = 0; i < 4; i++)
#pragma unroll
        for (int j = 0; j < 4; j++) acc[i][j] = 0ull;

    int k0 = kq * 4;
    int s0 = k0, s2 = k0 + 2;               // (k0+j)&30 for j=0,1 and 2,3

    for (int ch = 0; ch < 14; ch++) {
#pragma unroll
        for (int rep = 0; rep < 8; rep++) {
            int orow = rr + rep * 32;
            w_s[k0+0][orow ^ s0] = pw[rep].x;
            w_s[k0+1][orow ^ s0] = pw[rep].y;
            w_s[k0+2][orow ^ s2] = pw[rep].z;
            w_s[k0+3][orow ^ s2] = pw[rep].w;
        }
        hp_s[k0+0][rr] = pk2(ph.x, ph.x);
        hp_s[k0+1][rr] = pk2(ph.y, ph.y);
        hp_s[k0+2][rr] = pk2(ph.z, ph.z);
        hp_s[k0+3][rr] = pk2(ph.w, ph.w);
        __syncthreads();

        if (ch < 13) {
            int kb = f0 + (ch + 1) * 32;
#pragma unroll
            for (int rep = 0; rep < 8; rep++)
                pw[rep] = *(const float4*)(fwb + (size_t)rep*32*NF + kb);
            ph = *(const float4*)(hpb + kb);
        }

#pragma unroll 4
        for (int k = 0; k < 32; k++) {
            int s  = k & 30;
            int pc = tx2 ^ s;
            ull w0 = *(const ull*)&w_s[k][pc];
            ull w1 = *(const ull*)&w_s[k][64  + pc];
            ull w2 = *(const ull*)&w_s[k][128 + pc];
            ull w3 = *(const ull*)&w_s[k][192 + pc];
            const ulonglong2* hr = (const ulonglong2*)&hp_s[k][ty*4];
            ulonglong2 x01 = hr[0], x23 = hr[1];
            ull xb[4] = {x01.x, x01.y, x23.x, x23.y};
#pragma unroll
            for (int bi = 0; bi < 4; bi++) {
                acc[bi][0] = ffma2(w0, xb[bi], acc[bi][0]);
                acc[bi][1] = ffma2(w1, xb[bi], acc[bi][1]);
                acc[bi][2] = ffma2(w2, xb[bi], acc[bi][2]);
                acc[bi][3] = ffma2(w3, xb[bi], acc[bi][3]);
            }
        }
        __syncthreads();
    }

    float* pt = g_part + ((size_t)(h*32 + blockIdx.z)) * BB * FF;
#pragma unroll
    for (int bi = 0; bi < 4; bi++) {
        int b = ty * 4 + bi;
#pragma unroll
        for (int p = 0; p < 4; p++) {
            float2 v = upk2(acc[bi][p]);
            int oc = o0 + p*64 + tx2;
            pt[b*FF + oc]     = v.x;
            pt[b*FF + oc + 1] = v.y;
        }
    }
}

// ---------------------------------------------------------------------------
// K4a: stage-A reduction. grid (16 partial-groups, 32 b), 256 threads.
// ---------------------------------------------------------------------------
__global__ void __launch_bounds__(256) k4a() {
    int pg = blockIdx.x, b = blockIdx.y, t = threadIdx.x;
    const float4* gp = (const float4*)g_part;
    float4 s = make_float4(0.f, 0.f, 0.f, 0.f);
#pragma unroll
    for (int j = 0; j < 8; j++) {
        float4 v = gp[(size_t)((pg*8 + j)*BB + b) * (FF/4) + t];
        s.x += v.x; s.y += v.y; s.z += v.z; s.w += v.w;
    }
    ((float4*)g_red)[(size_t)(pg*BB + b) * (FF/4) + t] = s;
}

// ---------------------------------------------------------------------------
// K4b: out[b,o] = log_softmax_o( sum_pg red[pg][b][o] + sum_h fc_b[h][o] )
// ---------------------------------------------------------------------------
__global__ void __launch_bounds__(256) k4b(const float* __restrict__ fc_b,
                                           float* __restrict__ out) {
    int b = blockIdx.x, t = threadIdx.x;
    int lane = t & 31, wrp = t >> 5;
    __shared__ float red[8];

    float4 s = make_float4(0.f, 0.f, 0.f, 0.f);
    const float4* gr = (const float4*)g_red;
#pragma unroll
    for (int pg = 0; pg < 16; pg++) {
        float4 v = gr[(size_t)(pg*BB + b) * (FF/4) + t];
        s.x += v.x; s.y += v.y; s.z += v.z; s.w += v.w;
    }
    const float4* fb = (const float4*)fc_b;
#pragma unroll
    for (int h = 0; h < HH; h++) {
        float4 v = fb[h*(FF/4) + t];
        s.x += v.x; s.y += v.y; s.z += v.z; s.w += v.w;
    }

    float m = fmaxf(fmaxf(s.x, s.y), fmaxf(s.z, s.w));
#pragma unroll
    for (int d = 16; d; d >>= 1) m = fmaxf(m, __shfl_xor_sync(0xffffffffu, m, d));
    if (lane == 0) red[wrp] = m;
    __syncthreads();
    float mx = fmaxf(fmaxf(fmaxf(red[0], red[1]), fmaxf(red[2], red[3])),
                     fmaxf(fmaxf(red[4], red[5]), fmaxf(red[6], red[7])));
    __syncthreads();

    float es = expf(s.x - mx) + expf(s.y - mx) + expf(s.z - mx) + expf(s.w - mx);
#pragma unroll
    for (int d = 16; d; d >>= 1) es += __shfl_xor_sync(0xffffffffu, es, d);
    if (lane == 0) red[wrp] = es;
    __syncthreads();
    float tot = red[0] + red[1] + red[2] + red[3] + red[4] + red[5] + red[6] + red[7];
    float lse = logf(tot) + mx;

    ((float4*)out)[b*(FF/4) + t] =
        make_float4(s.x - lse, s.y - lse, s.z - lse, s.w - lse);
}

// ---------------------------------------------------------------------------
extern "C" void kernel_launch(void* const* d_in, const int* in_sizes, int n_in,
                              void* d_out, int out_size) {
    const float *x = nullptr, *adj = nullptr, *W = nullptr, *a = nullptr;
    const float *fcw = nullptr, *fcb = nullptr;
    for (int i = 0; i < n_in; i++) {
        switch (in_sizes[i]) {
            case 458752:    x   = (const float*)d_in[i]; break;  // x (32,14,1024)
            case 6272:      adj = (const float*)d_in[i]; break;  // adj (32,14,14)
            case 134217728: W   = (const float*)d_in[i]; break;  // W (4,32,1024,1024)
            case 262144:    a   = (const float*)d_in[i]; break;  // a (4,32,2048,1)
            case 58720256:  fcw = (const float*)d_in[i]; break;  // fc_w (4,1024,14336)
            case 4096:      fcb = (const float*)d_in[i]; break;  // fc_b (4,1024)
        }
    }
    cudaFuncSetAttribute(k1, cudaFuncAttributeMaxDynamicSharedMemorySize, 2*512*8*8);
    cudaFuncSetAttribute(k2, cudaFuncAttributeMaxDynamicSharedMemorySize, NN*FF*4);
    // launch idx 3 is the ncu capture slot -> k3 this round
    k1<<<HH*BB*2, 512, 2*512*8*8>>>(x, W);
    k2<<<HH*BB, 448, NN*FF*4>>>(adj, a);
    kdummy<<<1, 1>>>();
    k3<<<dim3(4, 4, 32), 256>>>(fcw);
    k4a<<<dim3(16, BB), 256>>>();
    k4b<<<BB, 256>>>(fcb, (float*)d_out);
}